// round 7
// baseline (speedup 1.0000x reference)
#include <cuda_runtime.h>
#include <cuda_fp16.h>
#include <math.h>

#define N_NODES 100000
#define N_EDGES 1600000
#define NFEAT 128
#define NHID 64
#define NCLASS 40

#define SCAN_BLK 1024
#define NB ((N_NODES + SCAN_BLK - 1) / SCAN_BLK)   // 98

// ---- scratch (__device__ globals; no allocation allowed) ----
__device__ float g_dinv[N_NODES];
__device__ __align__(16) __half g_Ah[N_NODES * NHID]; // fp16 g = dinv*(X@W)
__device__ __align__(16) float g_L[N_NODES * NHID];   // logits buffer (layer 3)
__device__ __align__(16) float g_C[N_NODES * NHID];   // post-activation features
__device__ int g_cnt[N_NODES];
__device__ int g_scan[N_NODES];
__device__ int g_bsum[NB];
__device__ int g_rowptr[N_NODES + 1];
__device__ int g_cursor[N_NODES];
__device__ int g_csr[N_EDGES];

// ------------------------------------------------------------ CSR build
__global__ void zero_cnt_kernel() {
    int i = blockIdx.x * blockDim.x + threadIdx.x;
    if (i < N_NODES) g_cnt[i] = 0;
}

__global__ void hist_kernel(const int* __restrict__ dst) {
    int e = blockIdx.x * blockDim.x + threadIdx.x;
    if (e < N_EDGES) atomicAdd(&g_cnt[dst[e]], 1);
}

__global__ void dinv_kernel() {
    int i = blockIdx.x * blockDim.x + threadIdx.x;
    if (i < N_NODES) g_dinv[i] = rsqrtf((float)g_cnt[i] + 1.0f); // +1 self-loop
}

__global__ void scan1_kernel() {      // grid NB, block 1024
    __shared__ int sm[2][SCAN_BLK];
    int t = threadIdx.x;
    int i = blockIdx.x * SCAN_BLK + t;
    int v = (i < N_NODES) ? g_cnt[i] : 0;
    sm[0][t] = v;
    __syncthreads();
    int pi = 0;
#pragma unroll
    for (int off = 1; off < SCAN_BLK; off <<= 1) {
        int x = sm[pi][t];
        if (t >= off) x += sm[pi][t - off];
        sm[pi ^ 1][t] = x;
        __syncthreads();
        pi ^= 1;
    }
    int incl = sm[pi][t];
    if (i < N_NODES) g_scan[i] = incl - v;       // exclusive
    if (t == SCAN_BLK - 1) g_bsum[blockIdx.x] = incl;
}

__global__ void scan2_kernel() {      // parallel scan over NB block sums
    __shared__ int sm[2][128];
    int t = threadIdx.x;
    int v = (t < NB) ? g_bsum[t] : 0;
    sm[0][t] = v;
    __syncthreads();
    int pi = 0;
#pragma unroll
    for (int off = 1; off < 128; off <<= 1) {
        int x = sm[pi][t];
        if (t >= off) x += sm[pi][t - off];
        sm[pi ^ 1][t] = x;
        __syncthreads();
        pi ^= 1;
    }
    if (t < NB) g_bsum[t] = sm[pi][t] - v;       // exclusive
}

__global__ void scan3_kernel() {
    int i = blockIdx.x * blockDim.x + threadIdx.x;
    if (i < N_NODES) {
        int r = g_scan[i] + g_bsum[i >> 10];
        g_rowptr[i] = r;
        g_cursor[i] = r;
    }
    if (i == 0) g_rowptr[N_NODES] = N_EDGES;
}

__global__ void fill_kernel(const int* __restrict__ src,
                            const int* __restrict__ dst) {
    int e = blockIdx.x * blockDim.x + threadIdx.x;
    if (e < N_EDGES) {
        int d = dst[e];
        int pos = atomicAdd(&g_cursor[d], 1);
        g_csr[pos] = src[e];
    }
}

// ------------------------------------------------------------------- GEMM
// Tiled register-blocked SGEMM, fused dinv scaling, fp16 output.
template <int K, int M>
__global__ void __launch_bounds__((M / 4) * 8) gemm_tiled_h_kernel(
    const float* __restrict__ X, const float* __restrict__ W,
    __half* __restrict__ out)
{
    constexpr int KC = 16;
    constexpr int ROWS = 64;
    constexpr int NT = (M / 4) * 8;
    constexpr int XS_STRIDE = ROWS + 4;

    __shared__ __align__(16) float Xs[KC * XS_STRIDE];
    __shared__ __align__(16) float Ws[KC * M];

    const int tid = threadIdx.x;
    const int tx = tid % (M / 4);
    const int ty = tid / (M / 4);
    const int rowBase = blockIdx.x * ROWS;

    float acc[8][4];
#pragma unroll
    for (int r = 0; r < 8; r++)
#pragma unroll
        for (int c = 0; c < 4; c++) acc[r][c] = 0.f;

    const float4* X4 = reinterpret_cast<const float4*>(X);
    const float4* W4 = reinterpret_cast<const float4*>(W);

#pragma unroll 1
    for (int c0 = 0; c0 < K; c0 += KC) {
#pragma unroll 1
        for (int idx = tid; idx < ROWS * KC / 4; idx += NT) {
            int rl = idx >> 2;
            int k4 = idx & 3;
            int row = rowBase + rl;
            float4 v = (row < N_NODES)
                ? __ldg(&X4[(size_t)row * (K / 4) + c0 / 4 + k4])
                : make_float4(0.f, 0.f, 0.f, 0.f);
            Xs[(k4 * 4 + 0) * XS_STRIDE + rl] = v.x;
            Xs[(k4 * 4 + 1) * XS_STRIDE + rl] = v.y;
            Xs[(k4 * 4 + 2) * XS_STRIDE + rl] = v.z;
            Xs[(k4 * 4 + 3) * XS_STRIDE + rl] = v.w;
        }
#pragma unroll 1
        for (int idx = tid; idx < KC * M / 4; idx += NT) {
            int kk = idx / (M / 4);
            int m4 = idx % (M / 4);
            reinterpret_cast<float4*>(Ws)[kk * (M / 4) + m4] =
                __ldg(&W4[(size_t)(c0 + kk) * (M / 4) + m4]);
        }
        __syncthreads();

#pragma unroll
        for (int kk = 0; kk < KC; kk++) {
            float4 b = *reinterpret_cast<const float4*>(&Ws[kk * M + tx * 4]);
            float4 a0 = *reinterpret_cast<const float4*>(&Xs[kk * XS_STRIDE + ty * 8]);
            float4 a1 = *reinterpret_cast<const float4*>(&Xs[kk * XS_STRIDE + ty * 8 + 4]);
            float a[8] = {a0.x, a0.y, a0.z, a0.w, a1.x, a1.y, a1.z, a1.w};
#pragma unroll
            for (int r = 0; r < 8; r++) {
                acc[r][0] = fmaf(a[r], b.x, acc[r][0]);
                acc[r][1] = fmaf(a[r], b.y, acc[r][1]);
                acc[r][2] = fmaf(a[r], b.z, acc[r][2]);
                acc[r][3] = fmaf(a[r], b.w, acc[r][3]);
            }
        }
        __syncthreads();
    }

#pragma unroll
    for (int r = 0; r < 8; r++) {
        int row = rowBase + ty * 8 + r;
        if (row < N_NODES) {
            float s = __ldg(&g_dinv[row]);
            __half2 h0 = __float22half2_rn(make_float2(acc[r][0] * s, acc[r][1] * s));
            __half2 h1 = __float22half2_rn(make_float2(acc[r][2] * s, acc[r][3] * s));
            uint2 pack;
            pack.x = *reinterpret_cast<unsigned*>(&h0);
            pack.y = *reinterpret_cast<unsigned*>(&h1);
            reinterpret_cast<uint2*>(out)[(size_t)row * (M / 4) + tx] = pack;
        }
    }
}

// ------------------------------------------------------- fused gather
struct F8 { float v[8]; };
__device__ __forceinline__ void acc8(F8& a, uint4 p) {
    const __half2* h = reinterpret_cast<const __half2*>(&p);
#pragma unroll
    for (int q = 0; q < 4; q++) {
        float2 f = __half22float2(h[q]);
        a.v[2 * q]     += f.x;
        a.v[2 * q + 1] += f.y;
    }
}

// Warp per row. 4 lane-groups of 8 threads each walk interleaved edges;
// each group reads a coalesced 128B fp16 source row. shfl_xor reduction.
__global__ void gather_relu64_warp_kernel(const uint4* __restrict__ g,
                                          const float* __restrict__ bias,
                                          float4* __restrict__ C)
{
    int row = (blockIdx.x * blockDim.x + threadIdx.x) >> 5;
    if (row >= N_NODES) return;
    int lane = threadIdx.x & 31;
    int grp = lane >> 3;           // 0..3
    int j = lane & 7;              // feature slot (8 fp16 = 16B)

    int beg = g_rowptr[row], end = g_rowptr[row + 1];

    F8 a, b;
#pragma unroll
    for (int q = 0; q < 8; q++) { a.v[q] = 0.f; b.v[q] = 0.f; }

    int e = beg + grp;
    // two independent chains (unroll-2 over stride-4 walk)
    for (; e + 4 < end; e += 8) {
        int s0 = __ldg(&g_csr[e]);
        int s1 = __ldg(&g_csr[e + 4]);
        acc8(a, __ldg(&g[(size_t)s0 * 8 + j]));
        acc8(b, __ldg(&g[(size_t)s1 * 8 + j]));
    }
    if (e < end) {
        int s = __ldg(&g_csr[e]);
        acc8(a, __ldg(&g[(size_t)s * 8 + j]));
    }
    if (grp == 0) acc8(b, __ldg(&g[(size_t)row * 8 + j]));  // self loop
#pragma unroll
    for (int q = 0; q < 8; q++) a.v[q] += b.v[q];

    // combine the 4 groups: lanes {j, j+8, j+16, j+24}
#pragma unroll
    for (int q = 0; q < 8; q++) {
        a.v[q] += __shfl_xor_sync(0xFFFFFFFFu, a.v[q], 8);
        a.v[q] += __shfl_xor_sync(0xFFFFFFFFu, a.v[q], 16);
    }

    if (grp == 0) {
        float s = g_dinv[row];
        const float4* b4 = reinterpret_cast<const float4*>(bias);
        float4 bb0 = __ldg(&b4[2 * j]);
        float4 bb1 = __ldg(&b4[2 * j + 1]);
        float4 r0, r1;
        r0.x = fmaxf(fmaf(s, a.v[0], bb0.x), 0.f);
        r0.y = fmaxf(fmaf(s, a.v[1], bb0.y), 0.f);
        r0.z = fmaxf(fmaf(s, a.v[2], bb0.z), 0.f);
        r0.w = fmaxf(fmaf(s, a.v[3], bb0.w), 0.f);
        r1.x = fmaxf(fmaf(s, a.v[4], bb1.x), 0.f);
        r1.y = fmaxf(fmaf(s, a.v[5], bb1.y), 0.f);
        r1.z = fmaxf(fmaf(s, a.v[6], bb1.z), 0.f);
        r1.w = fmaxf(fmaf(s, a.v[7], bb1.w), 0.f);
        C[(size_t)row * 16 + 2 * j]     = r0;
        C[(size_t)row * 16 + 2 * j + 1] = r1;
    }
}

// Warp per row, 3 lane-groups of 10 (lanes 0-29), 4 features (8B) per thread.
__global__ void gather_logits40_warp_kernel(const uint2* __restrict__ g,
                                            const float* __restrict__ b3,
                                            float4* __restrict__ L)
{
    int row = (blockIdx.x * blockDim.x + threadIdx.x) >> 5;
    if (row >= N_NODES) return;
    int lane = threadIdx.x & 31;
    int grp = lane / 10;           // 0,1,2 (lanes 30,31 -> grp 3, idle)
    int j = lane - grp * 10;

    int beg = g_rowptr[row], end = g_rowptr[row + 1];

    float a0 = 0.f, a1 = 0.f, a2 = 0.f, a3 = 0.f;
    if (grp < 3) {
        for (int e = beg + grp; e < end; e += 3) {
            int s = __ldg(&g_csr[e]);
            uint2 p = __ldg(&g[(size_t)s * 10 + j]);
            float2 f0 = __half22float2(*reinterpret_cast<const __half2*>(&p.x));
            float2 f1 = __half22float2(*reinterpret_cast<const __half2*>(&p.y));
            a0 += f0.x; a1 += f0.y; a2 += f1.x; a3 += f1.y;
        }
        if (grp == 0) {
            uint2 p = __ldg(&g[(size_t)row * 10 + j]);   // self loop
            float2 f0 = __half22float2(*reinterpret_cast<const __half2*>(&p.x));
            float2 f1 = __half22float2(*reinterpret_cast<const __half2*>(&p.y));
            a0 += f0.x; a1 += f0.y; a2 += f1.x; a3 += f1.y;
        }
    }

    // lane j accumulates lanes j+10 and j+20
    a0 += __shfl_sync(0xFFFFFFFFu, a0, lane + 10) + __shfl_sync(0xFFFFFFFFu, a0, lane + 20);
    a1 += __shfl_sync(0xFFFFFFFFu, a1, lane + 10) + __shfl_sync(0xFFFFFFFFu, a1, lane + 20);
    a2 += __shfl_sync(0xFFFFFFFFu, a2, lane + 10) + __shfl_sync(0xFFFFFFFFu, a2, lane + 20);
    a3 += __shfl_sync(0xFFFFFFFFu, a3, lane + 10) + __shfl_sync(0xFFFFFFFFu, a3, lane + 20);

    if (grp == 0) {
        float s = g_dinv[row];
        float4 bb = __ldg(&reinterpret_cast<const float4*>(b3)[j]);
        float4 r;
        r.x = fmaf(s, a0, bb.x);
        r.y = fmaf(s, a1, bb.y);
        r.z = fmaf(s, a2, bb.z);
        r.w = fmaf(s, a3, bb.w);
        L[(size_t)row * 10 + j] = r;
    }
}

// --------------------------------------------- final log_softmax (warp/row)
__global__ void final_lsm_kernel(const float* __restrict__ L,
                                 float* __restrict__ out)
{
    int warp = (blockIdx.x * blockDim.x + threadIdx.x) >> 5;
    int lane = threadIdx.x & 31;
    if (warp >= N_NODES) return;
    size_t base = (size_t)warp * 40;

    float v0 = L[base + lane];
    float v1 = (lane < 8) ? L[base + 32 + lane] : -1e30f;

    float m = fmaxf(v0, v1);
#pragma unroll
    for (int off = 16; off > 0; off >>= 1)
        m = fmaxf(m, __shfl_xor_sync(0xFFFFFFFFu, m, off));

    float e = __expf(v0 - m) + ((lane < 8) ? __expf(v1 - m) : 0.f);
#pragma unroll
    for (int off = 16; off > 0; off >>= 1)
        e += __shfl_xor_sync(0xFFFFFFFFu, e, off);

    float ls = __logf(e);
    out[base + lane] = v0 - m - ls;
    if (lane < 8) out[base + 32 + lane] = v1 - m - ls;
}

// ------------------------------------------------------------------ launch
extern "C" void kernel_launch(void* const* d_in, const int* in_sizes, int n_in,
                              void* d_out, int out_size)
{
    const float* x   = (const float*)d_in[0];
    const int* ei    = (const int*)d_in[1];
    const float* W1  = (const float*)d_in[2];
    const float* b1  = (const float*)d_in[3];
    const float* W2  = (const float*)d_in[4];
    const float* b2  = (const float*)d_in[5];
    const float* W3  = (const float*)d_in[6];
    const float* b3  = (const float*)d_in[7];
    float* out       = (float*)d_out;

    const int* src = ei;
    const int* dst = ei + N_EDGES;

    __half* Ah; cudaGetSymbolAddress((void**)&Ah, g_Ah);
    float* L;   cudaGetSymbolAddress((void**)&L, g_L);
    float* C;   cudaGetSymbolAddress((void**)&C, g_C);

    const int TPB = 256;
    const int nodeBlocks = (N_NODES + TPB - 1) / TPB;
    const int edgeBlocks = (N_EDGES + TPB - 1) / TPB;
    const int tile_blocks = (N_NODES + 63) / 64;
    const int warpRow_blocks = (N_NODES * 32 + TPB - 1) / TPB;   // 12500

    // ---- CSR build + dinv ----
    zero_cnt_kernel<<<nodeBlocks, TPB>>>();
    hist_kernel<<<edgeBlocks, TPB>>>(dst);
    dinv_kernel<<<nodeBlocks, TPB>>>();
    scan1_kernel<<<NB, SCAN_BLK>>>();
    scan2_kernel<<<1, 128>>>();
    scan3_kernel<<<nodeBlocks, TPB>>>();
    fill_kernel<<<edgeBlocks, TPB>>>(src, dst);

    // ---- layer 1 ----
    gemm_tiled_h_kernel<NFEAT, NHID><<<tile_blocks, 128>>>(x, W1, Ah);
    gather_relu64_warp_kernel<<<warpRow_blocks, TPB>>>((const uint4*)Ah, b1, (float4*)C);

    // ---- layer 2 ----
    gemm_tiled_h_kernel<NHID, NHID><<<tile_blocks, 128>>>(C, W2, Ah);
    gather_relu64_warp_kernel<<<warpRow_blocks, TPB>>>((const uint4*)Ah, b2, (float4*)C);

    // ---- layer 3 ----
    gemm_tiled_h_kernel<NHID, NCLASS><<<tile_blocks, 80>>>(C, W3, Ah);
    gather_logits40_warp_kernel<<<warpRow_blocks, TPB>>>((const uint2*)Ah, b3, (float4*)L);
    final_lsm_kernel<<<warpRow_blocks, TPB>>>(L, out);
}

// round 8
// speedup vs baseline: 1.3917x; 1.3917x over previous
#include <cuda_runtime.h>
#include <cuda_fp16.h>
#include <math.h>

#define N_NODES 100000
#define N_EDGES 1600000
#define NFEAT 128
#define NHID 64
#define NCLASS 40

#define SCAN_BLK 1024
#define NB ((N_NODES + SCAN_BLK - 1) / SCAN_BLK)   // 98

// ---- scratch (__device__ globals; no allocation allowed) ----
__device__ float g_dinv[N_NODES];
__device__ __align__(16) __half g_Xh[N_NODES * NFEAT];  // fp16 copy of x
__device__ __align__(16) __half g_Ah[N_NODES * NHID];   // fp16 g = dinv*(X@W)
__device__ __align__(16) __half g_Ch[N_NODES * NHID];   // fp16 post-activation
__device__ __align__(16) float g_L[N_NODES * NHID];     // logits fp32
__device__ int g_cnt[N_NODES];
__device__ int g_scan[N_NODES];
__device__ int g_bsum[NB];
__device__ int g_rowptr[N_NODES + 1];
__device__ int g_cursor[N_NODES];
__device__ int g_csr[N_EDGES];

// ------------------------------------------------------------ CSR build
__global__ void zero_cnt_kernel() {
    int i = blockIdx.x * blockDim.x + threadIdx.x;
    if (i < N_NODES) g_cnt[i] = 0;
}

__global__ void hist_kernel(const int* __restrict__ dst) {
    int e = blockIdx.x * blockDim.x + threadIdx.x;
    if (e < N_EDGES) atomicAdd(&g_cnt[dst[e]], 1);
}

__global__ void dinv_kernel() {
    int i = blockIdx.x * blockDim.x + threadIdx.x;
    if (i < N_NODES) g_dinv[i] = rsqrtf((float)g_cnt[i] + 1.0f); // +1 self-loop
}

__global__ void scan1_kernel() {
    __shared__ int sm[2][SCAN_BLK];
    int t = threadIdx.x;
    int i = blockIdx.x * SCAN_BLK + t;
    int v = (i < N_NODES) ? g_cnt[i] : 0;
    sm[0][t] = v;
    __syncthreads();
    int pi = 0;
#pragma unroll
    for (int off = 1; off < SCAN_BLK; off <<= 1) {
        int x = sm[pi][t];
        if (t >= off) x += sm[pi][t - off];
        sm[pi ^ 1][t] = x;
        __syncthreads();
        pi ^= 1;
    }
    int incl = sm[pi][t];
    if (i < N_NODES) g_scan[i] = incl - v;
    if (t == SCAN_BLK - 1) g_bsum[blockIdx.x] = incl;
}

__global__ void scan2_kernel() {
    __shared__ int sm[2][128];
    int t = threadIdx.x;
    int v = (t < NB) ? g_bsum[t] : 0;
    sm[0][t] = v;
    __syncthreads();
    int pi = 0;
#pragma unroll
    for (int off = 1; off < 128; off <<= 1) {
        int x = sm[pi][t];
        if (t >= off) x += sm[pi][t - off];
        sm[pi ^ 1][t] = x;
        __syncthreads();
        pi ^= 1;
    }
    if (t < NB) g_bsum[t] = sm[pi][t] - v;
}

__global__ void scan3_kernel() {
    int i = blockIdx.x * blockDim.x + threadIdx.x;
    if (i < N_NODES) {
        int r = g_scan[i] + g_bsum[i >> 10];
        g_rowptr[i] = r;
        g_cursor[i] = r;
    }
    if (i == 0) g_rowptr[N_NODES] = N_EDGES;
}

__global__ void fill_kernel(const int* __restrict__ src,
                            const int* __restrict__ dst) {
    int e = blockIdx.x * blockDim.x + threadIdx.x;
    if (e < N_EDGES) {
        int d = dst[e];
        int pos = atomicAdd(&g_cursor[d], 1);
        g_csr[pos] = src[e];
    }
}

// ------------------------------------------------- x -> fp16 conversion
__global__ void cvt_x_kernel(const float4* __restrict__ x4, uint4* __restrict__ xh) {
    int i = blockIdx.x * blockDim.x + threadIdx.x;   // over N_NODES*NFEAT/8
    if (i >= N_NODES * NFEAT / 8) return;
    float4 v0 = __ldg(&x4[2 * i]);
    float4 v1 = __ldg(&x4[2 * i + 1]);
    __half2 h0 = __float22half2_rn(make_float2(v0.x, v0.y));
    __half2 h1 = __float22half2_rn(make_float2(v0.z, v0.w));
    __half2 h2 = __float22half2_rn(make_float2(v1.x, v1.y));
    __half2 h3 = __float22half2_rn(make_float2(v1.z, v1.w));
    uint4 o;
    o.x = *reinterpret_cast<unsigned*>(&h0);
    o.y = *reinterpret_cast<unsigned*>(&h1);
    o.z = *reinterpret_cast<unsigned*>(&h2);
    o.w = *reinterpret_cast<unsigned*>(&h3);
    xh[i] = o;
}

// ------------------------------------------------------------- HMMA GEMM
// out[row,:] = dinv[row] * (X[row,:] @ W)  — fp16 in, fp32 accum, fp16 out.
// Tile: 128 rows x M cols. 256 threads = 8 warps; warp w -> rows w*16..+15.
template <int K, int M, int WS_STRIDE>
__global__ void __launch_bounds__(256) gemm_mma_kernel(
    const __half* __restrict__ X, const float* __restrict__ W,
    __half* __restrict__ out)
{
    constexpr int AS_STRIDE = K + 8;       // halves; stride*2 % 16 == 0
    constexpr int NC = M / 8;              // n-chunks
    __shared__ __align__(16) __half Asm[128 * AS_STRIDE];
    __shared__ __align__(16) __half Wsm[K * WS_STRIDE];

    const int tid = threadIdx.x;
    const int warp = tid >> 5;
    const int lane = tid & 31;
    const int rowBase = blockIdx.x * 128;

    // load A tile (uint4 = 8 halves), zero-pad invalid rows
    {
        const uint4* X4 = reinterpret_cast<const uint4*>(X);
        constexpr int SEGS = K / 8;
        for (int idx = tid; idx < 128 * SEGS; idx += 256) {
            int rl = idx / SEGS;
            int seg = idx % SEGS;
            int row = rowBase + rl;
            uint4 v = make_uint4(0u, 0u, 0u, 0u);
            if (row < N_NODES) v = __ldg(&X4[(size_t)row * SEGS + seg]);
            *reinterpret_cast<uint4*>(&Asm[rl * AS_STRIDE + seg * 8]) = v;
        }
    }
    // load + convert W [K x M]
    for (int idx = tid; idx < K * M; idx += 256) {
        int k = idx / M;
        int m = idx % M;
        Wsm[k * WS_STRIDE + m] = __float2half(__ldg(&W[idx]));
    }
    __syncthreads();

    float acc[NC][4];
#pragma unroll
    for (int n = 0; n < NC; n++)
#pragma unroll
        for (int q = 0; q < 4; q++) acc[n][q] = 0.f;

    const unsigned aBase = (unsigned)__cvta_generic_to_shared(Asm);
    const unsigned wBase = (unsigned)__cvta_generic_to_shared(Wsm);
    const int rlane = lane & 15;
    const int hilo = lane >> 4;

#pragma unroll
    for (int k0 = 0; k0 < K; k0 += 16) {
        unsigned a0, a1, a2, a3;
        unsigned aAddr = aBase +
            ((warp * 16 + rlane) * AS_STRIDE + k0) * 2 + hilo * 16;
        asm volatile("ldmatrix.sync.aligned.m8n8.x4.shared.b16 {%0,%1,%2,%3}, [%4];"
                     : "=r"(a0), "=r"(a1), "=r"(a2), "=r"(a3) : "r"(aAddr));
#pragma unroll
        for (int n = 0; n < NC; n++) {
            unsigned b0, b1;
            unsigned bAddr = wBase + ((k0 + rlane) * WS_STRIDE + n * 8) * 2;
            asm volatile("ldmatrix.sync.aligned.m8n8.x2.trans.shared.b16 {%0,%1}, [%2];"
                         : "=r"(b0), "=r"(b1) : "r"(bAddr));
            asm volatile(
                "mma.sync.aligned.m16n8k16.row.col.f32.f16.f16.f32 "
                "{%0,%1,%2,%3}, {%4,%5,%6,%7}, {%8,%9}, {%0,%1,%2,%3};"
                : "+f"(acc[n][0]), "+f"(acc[n][1]), "+f"(acc[n][2]), "+f"(acc[n][3])
                : "r"(a0), "r"(a1), "r"(a2), "r"(a3), "r"(b0), "r"(b1));
        }
    }

    // epilogue: row0 = base + warp*16 + lane/4, row1 = row0 + 8
    int row0 = rowBase + warp * 16 + (lane >> 2);
    int row1 = row0 + 8;
    float s0 = (row0 < N_NODES) ? g_dinv[row0] : 0.f;
    float s1 = (row1 < N_NODES) ? g_dinv[row1] : 0.f;
    unsigned* outU = reinterpret_cast<unsigned*>(out);
#pragma unroll
    for (int n = 0; n < NC; n++) {
        int col = n * 8 + (lane & 3) * 2;
        if (row0 < N_NODES) {
            __half2 h = __float22half2_rn(make_float2(acc[n][0] * s0, acc[n][1] * s0));
            outU[((size_t)row0 * M + col) >> 1] = *reinterpret_cast<unsigned*>(&h);
        }
        if (row1 < N_NODES) {
            __half2 h = __float22half2_rn(make_float2(acc[n][2] * s1, acc[n][3] * s1));
            outU[((size_t)row1 * M + col) >> 1] = *reinterpret_cast<unsigned*>(&h);
        }
    }
}

// ------------------------------------------------------- fused gather
struct F8 { float v[8]; };
__device__ __forceinline__ void acc8(F8& a, uint4 p) {
    const __half2* h = reinterpret_cast<const __half2*>(&p);
#pragma unroll
    for (int q = 0; q < 4; q++) {
        float2 f = __half22float2(h[q]);
        a.v[2 * q]     += f.x;
        a.v[2 * q + 1] += f.y;
    }
}

// Ch[row] = relu(dinv[row]*(sum_e g[src_e] + g[row]) + bias), fp16 out.
// 8 threads per row, 8 features (16B fp16) per thread.
__global__ void gather_relu64_kernel(const uint4* __restrict__ g,
                                     const float* __restrict__ bias,
                                     uint4* __restrict__ Ch)
{
    int tid = blockIdx.x * blockDim.x + threadIdx.x;
    int row = tid >> 3;
    int j = tid & 7;
    if (row >= N_NODES) return;
    int beg = g_rowptr[row], end = g_rowptr[row + 1];

    F8 a0, a1;
#pragma unroll
    for (int q = 0; q < 8; q++) { a0.v[q] = 0.f; a1.v[q] = 0.f; }

    int e = beg;
    for (; e + 1 < end; e += 2) {
        int s0 = __ldg(&g_csr[e]);
        int s1 = __ldg(&g_csr[e + 1]);
        acc8(a0, __ldg(&g[(size_t)s0 * 8 + j]));
        acc8(a1, __ldg(&g[(size_t)s1 * 8 + j]));
    }
    if (e < end) {
        int s = __ldg(&g_csr[e]);
        acc8(a0, __ldg(&g[(size_t)s * 8 + j]));
    }
    acc8(a0, __ldg(&g[(size_t)row * 8 + j]));   // self loop
#pragma unroll
    for (int q = 0; q < 8; q++) a0.v[q] += a1.v[q];

    float s = g_dinv[row];
    const float4* b4 = reinterpret_cast<const float4*>(bias);
    float4 bb0 = __ldg(&b4[2 * j]);
    float4 bb1 = __ldg(&b4[2 * j + 1]);
    float r0 = fmaxf(fmaf(s, a0.v[0], bb0.x), 0.f);
    float r1 = fmaxf(fmaf(s, a0.v[1], bb0.y), 0.f);
    float r2 = fmaxf(fmaf(s, a0.v[2], bb0.z), 0.f);
    float r3 = fmaxf(fmaf(s, a0.v[3], bb0.w), 0.f);
    float r4 = fmaxf(fmaf(s, a0.v[4], bb1.x), 0.f);
    float r5 = fmaxf(fmaf(s, a0.v[5], bb1.y), 0.f);
    float r6 = fmaxf(fmaf(s, a0.v[6], bb1.z), 0.f);
    float r7 = fmaxf(fmaf(s, a0.v[7], bb1.w), 0.f);
    __half2 h0 = __float22half2_rn(make_float2(r0, r1));
    __half2 h1 = __float22half2_rn(make_float2(r2, r3));
    __half2 h2 = __float22half2_rn(make_float2(r4, r5));
    __half2 h3 = __float22half2_rn(make_float2(r6, r7));
    uint4 o;
    o.x = *reinterpret_cast<unsigned*>(&h0);
    o.y = *reinterpret_cast<unsigned*>(&h1);
    o.z = *reinterpret_cast<unsigned*>(&h2);
    o.w = *reinterpret_cast<unsigned*>(&h3);
    Ch[(size_t)row * 8 + j] = o;
}

// L[row] = dinv[row]*(sum g40[src_e] + g40[row]) + b3 (fp32 out).
// 10 threads per row, 4 features (8B fp16) per thread.
__global__ void gather_logits40_kernel(const uint2* __restrict__ g,
                                       const float* __restrict__ b3,
                                       float4* __restrict__ L)
{
    int tid = blockIdx.x * blockDim.x + threadIdx.x;
    int row = tid / 10;
    int j = tid - row * 10;
    if (row >= N_NODES) return;
    int beg = g_rowptr[row], end = g_rowptr[row + 1];

    float a0 = 0.f, a1 = 0.f, a2 = 0.f, a3 = 0.f;
    for (int e = beg; e < end; e++) {
        int s = __ldg(&g_csr[e]);
        uint2 p = __ldg(&g[(size_t)s * 10 + j]);
        float2 f0 = __half22float2(*reinterpret_cast<const __half2*>(&p.x));
        float2 f1 = __half22float2(*reinterpret_cast<const __half2*>(&p.y));
        a0 += f0.x; a1 += f0.y; a2 += f1.x; a3 += f1.y;
    }
    {
        uint2 p = __ldg(&g[(size_t)row * 10 + j]);   // self loop
        float2 f0 = __half22float2(*reinterpret_cast<const __half2*>(&p.x));
        float2 f1 = __half22float2(*reinterpret_cast<const __half2*>(&p.y));
        a0 += f0.x; a1 += f0.y; a2 += f1.x; a3 += f1.y;
    }
    float s = g_dinv[row];
    float4 bb = __ldg(&reinterpret_cast<const float4*>(b3)[j]);
    float4 r;
    r.x = fmaf(s, a0, bb.x);
    r.y = fmaf(s, a1, bb.y);
    r.z = fmaf(s, a2, bb.z);
    r.w = fmaf(s, a3, bb.w);
    L[(size_t)row * 10 + j] = r;
}

// --------------------------------------------- final log_softmax (warp/row)
__global__ void final_lsm_kernel(const float* __restrict__ L,
                                 float* __restrict__ out)
{
    int warp = (blockIdx.x * blockDim.x + threadIdx.x) >> 5;
    int lane = threadIdx.x & 31;
    if (warp >= N_NODES) return;
    size_t base = (size_t)warp * 40;

    float v0 = L[base + lane];
    float v1 = (lane < 8) ? L[base + 32 + lane] : -1e30f;

    float m = fmaxf(v0, v1);
#pragma unroll
    for (int off = 16; off > 0; off >>= 1)
        m = fmaxf(m, __shfl_xor_sync(0xFFFFFFFFu, m, off));

    float e = __expf(v0 - m) + ((lane < 8) ? __expf(v1 - m) : 0.f);
#pragma unroll
    for (int off = 16; off > 0; off >>= 1)
        e += __shfl_xor_sync(0xFFFFFFFFu, e, off);

    float ls = __logf(e);
    out[base + lane] = v0 - m - ls;
    if (lane < 8) out[base + 32 + lane] = v1 - m - ls;
}

// ------------------------------------------------------------------ launch
extern "C" void kernel_launch(void* const* d_in, const int* in_sizes, int n_in,
                              void* d_out, int out_size)
{
    const float* x   = (const float*)d_in[0];
    const int* ei    = (const int*)d_in[1];
    const float* W1  = (const float*)d_in[2];
    const float* b1  = (const float*)d_in[3];
    const float* W2  = (const float*)d_in[4];
    const float* b2  = (const float*)d_in[5];
    const float* W3  = (const float*)d_in[6];
    const float* b3  = (const float*)d_in[7];
    float* out       = (float*)d_out;

    const int* src = ei;
    const int* dst = ei + N_EDGES;

    __half* Xh; cudaGetSymbolAddress((void**)&Xh, g_Xh);
    __half* Ah; cudaGetSymbolAddress((void**)&Ah, g_Ah);
    __half* Ch; cudaGetSymbolAddress((void**)&Ch, g_Ch);
    float* L;   cudaGetSymbolAddress((void**)&L, g_L);

    const int TPB = 256;
    const int nodeBlocks = (N_NODES + TPB - 1) / TPB;
    const int edgeBlocks = (N_EDGES + TPB - 1) / TPB;
    const int mma_blocks = (N_NODES + 127) / 128;            // 782
    const int cvt_blocks = (N_NODES * NFEAT / 8 + TPB - 1) / TPB;
    const int g64_blocks = (N_NODES * 8 + TPB - 1) / TPB;
    const int g40_blocks = (N_NODES * 10 + TPB - 1) / TPB;

    // ---- CSR build + dinv + x conversion ----
    zero_cnt_kernel<<<nodeBlocks, TPB>>>();
    hist_kernel<<<edgeBlocks, TPB>>>(dst);
    cvt_x_kernel<<<cvt_blocks, TPB>>>((const float4*)x, (uint4*)Xh);
    dinv_kernel<<<nodeBlocks, TPB>>>();
    scan1_kernel<<<NB, SCAN_BLK>>>();
    scan2_kernel<<<1, 128>>>();
    scan3_kernel<<<nodeBlocks, TPB>>>();
    fill_kernel<<<edgeBlocks, TPB>>>(src, dst);

    // ---- layer 1 ----
    gemm_mma_kernel<NFEAT, NHID, NHID + 8><<<mma_blocks, 256>>>(Xh, W1, Ah);
    gather_relu64_kernel<<<g64_blocks, TPB>>>((const uint4*)Ah, b1, (uint4*)Ch);

    // ---- layer 2 ----
    gemm_mma_kernel<NHID, NHID, NHID + 8><<<mma_blocks, 256>>>(Ch, W2, Ah);
    gather_relu64_kernel<<<g64_blocks, TPB>>>((const uint4*)Ah, b2, (uint4*)Ch);

    // ---- layer 3 ----
    gemm_mma_kernel<NHID, NCLASS, NCLASS + 16><<<mma_blocks, 256>>>(Ch, W3, Ah);
    gather_logits40_kernel<<<g40_blocks, TPB>>>((const uint2*)Ah, b3, (float4*)L);
    final_lsm_kernel<<<(N_NODES * 32 + TPB - 1) / TPB, TPB>>>(L, out);
}